// round 6
// baseline (speedup 1.0000x reference)
#include <cuda_runtime.h>
#include <cuda_bf16.h>

// CumulantSOAP: per-column mean + central 2nd moment of X (200000 x 576 fp32),
// then project (cum - mu) @ W -> (1, 4) fp32.
//
// cum[col] = [mean, mean(centered) (==0 to fp32 noise; emitted as exact 0),
//             mean(x^2) - mean^2]
//
// HBM-read roofline problem (460.8 MB ~ 73 us floor). Three kernels, all
// fully deterministic (no atomics, fixed reduction order, scratch fully
// overwritten every launch -> graph-replay safe, no zeroing pass):
//  1) accum:  grid 296 (2 CTAs/SM, enforced via __launch_bounds__),
//     blockDim 576 (4 row-lanes x 144 quads). float4 loads (LDG.128),
//     4x row unroll -> 4 independent LDG.128 in flight/thread
//     (~72KB in-flight/SM, ~2.8x latency-BW product). fp32 local
//     accumulation (~169 rows/thread/component, rel err ~1e-6), float4
//     smem reduction across the 4 lanes (conflict-free), coalesced fp32
//     partial store: g_partial[block][2*p].
//  2) reduce: 9 blocks x 1024 threads, fp64 fixed-order reduction of the
//     296 partials per (quantity, column) -> g_reduced[1152].
//  3) project: single block, fp64 (cum - mu) @ W.

#define P_MAX        1024
#define GRID_ACCUM   296

__device__ float  g_partial[GRID_ACCUM * 2 * P_MAX / 2];  // 296 * 1152 (p=576)
__device__ double g_reduced[2 * P_MAX];

// ---------------------------------------------------------------------------
// 1) Streaming accumulation. blockDim.x = 4 * p4 (p4 = p/4).
//    __launch_bounds__(576, 2): cap regs at 112/thread so 2 CTAs/SM is
//    guaranteed — the latency-hiding model depends on 36 warps/SM.
// ---------------------------------------------------------------------------
__global__ void __launch_bounds__(576, 2)
accum_kernel(const float4* __restrict__ X4, int n_rows, int p4,
             int rows_per_block) {
    const int lane = threadIdx.x / p4;   // row-lane 0..3
    const int c    = threadIdx.x % p4;   // quad index 0..p4-1

    int r0 = blockIdx.x * rows_per_block;
    int r1 = r0 + rows_per_block;
    if (r1 > n_rows) r1 = n_rows;

    float s0 = 0.f, s1 = 0.f, s2 = 0.f, s3 = 0.f;
    float q0 = 0.f, q1 = 0.f, q2 = 0.f, q3 = 0.f;

    const size_t stride = (size_t)p4;
    int r = r0 + lane;

    // 4x unroll over the 4-row-lane stride: 4 independent LDG.128 in flight.
    for (; r + 12 < r1; r += 16) {
        float4 a = X4[(size_t)r * stride + c];
        float4 b = X4[(size_t)(r + 4) * stride + c];
        float4 e = X4[(size_t)(r + 8) * stride + c];
        float4 f = X4[(size_t)(r + 12) * stride + c];
        s0 += a.x; q0 = fmaf(a.x, a.x, q0);
        s1 += a.y; q1 = fmaf(a.y, a.y, q1);
        s2 += a.z; q2 = fmaf(a.z, a.z, q2);
        s3 += a.w; q3 = fmaf(a.w, a.w, q3);
        s0 += b.x; q0 = fmaf(b.x, b.x, q0);
        s1 += b.y; q1 = fmaf(b.y, b.y, q1);
        s2 += b.z; q2 = fmaf(b.z, b.z, q2);
        s3 += b.w; q3 = fmaf(b.w, b.w, q3);
        s0 += e.x; q0 = fmaf(e.x, e.x, q0);
        s1 += e.y; q1 = fmaf(e.y, e.y, q1);
        s2 += e.z; q2 = fmaf(e.z, e.z, q2);
        s3 += e.w; q3 = fmaf(e.w, e.w, q3);
        s0 += f.x; q0 = fmaf(f.x, f.x, q0);
        s1 += f.y; q1 = fmaf(f.y, f.y, q1);
        s2 += f.z; q2 = fmaf(f.z, f.z, q2);
        s3 += f.w; q3 = fmaf(f.w, f.w, q3);
    }
    // Tail: remaining rows of this lane, stride 4.
    for (; r < r1; r += 4) {
        float4 a = X4[(size_t)r * stride + c];
        s0 += a.x; q0 = fmaf(a.x, a.x, q0);
        s1 += a.y; q1 = fmaf(a.y, a.y, q1);
        s2 += a.z; q2 = fmaf(a.z, a.z, q2);
        s3 += a.w; q3 = fmaf(a.w, a.w, q3);
    }

    // Intra-block reduction across the 4 row-lanes (float4 STS, conflict-free).
    extern __shared__ float4 red4[];             // 2 * 4 * p4 float4s
    const int p = p4 * 4;
    float4* red_s4  = red4;                      // [4][p4]
    float4* red_ss4 = red4 + 4 * p4;             // [4][p4]

    red_s4 [lane * p4 + c] = make_float4(s0, s1, s2, s3);
    red_ss4[lane * p4 + c] = make_float4(q0, q1, q2, q3);
    __syncthreads();

    // Thread col (< p) finalizes one column; coalesced partial store.
    const int col = threadIdx.x;
    if (col < p) {
        const float* red_s  = (const float*)red_s4;
        const float* red_ss = (const float*)red_ss4;
        float ts = red_s[col] + red_s[p + col] + red_s[2 * p + col] + red_s[3 * p + col];
        float tq = red_ss[col] + red_ss[p + col] + red_ss[2 * p + col] + red_ss[3 * p + col];
        float* dst = g_partial + (size_t)blockIdx.x * (2 * p);
        dst[col]     = ts;
        dst[p + col] = tq;
    }
}

// ---------------------------------------------------------------------------
// 2) Fixed-order fp64 reduction over the 296 block partials.
//    grid = ceil(2p/128) blocks, blockDim = 1024 (128 cols x 8 block-chunks).
// ---------------------------------------------------------------------------
__global__ void __launch_bounds__(1024, 1)
reduce_kernel(int n_blocks, int two_p) {
    const int c   = threadIdx.x & 127;       // column within this block's tile
    const int j   = threadIdx.x >> 7;        // block-chunk 0..7
    const int col = blockIdx.x * 128 + c;    // logical column 0..2p-1

    double s = 0.0;
    if (col < two_p) {
        for (int b = j; b < n_blocks; b += 8)
            s += (double)g_partial[(size_t)b * two_p + col];
    }

    __shared__ double sm[1024];
    sm[threadIdx.x] = s;
    __syncthreads();

    if (j == 0 && col < two_p) {
        double t = sm[c]         + sm[128 + c] + sm[256 + c] + sm[384 + c]
                 + sm[512 + c]   + sm[640 + c] + sm[768 + c] + sm[896 + c];
        g_reduced[col] = t;
    }
}

// ---------------------------------------------------------------------------
// 3) Projection: cum = [m, 0, var] per column, (cum - mu) @ W in fp64.
// ---------------------------------------------------------------------------
__global__ void __launch_bounds__(256, 1)
project_kernel(const float* __restrict__ mu,
               const float* __restrict__ W,
               float* __restrict__ out,
               int p, int d, double inv_n) {
    __shared__ double red[256 * 4];
    double acc[4] = {0.0, 0.0, 0.0, 0.0};

    for (int col = threadIdx.x; col < p; col += blockDim.x) {
        double m   = g_reduced[col] * inv_n;
        double var = g_reduced[p + col] * inv_n - m * m;
        int j0 = 3 * col;
        double c0 = m   - (double)mu[j0 + 0];
        double c1 = 0.0 - (double)mu[j0 + 1];
        double c2 = var - (double)mu[j0 + 2];
        const float* w0 = W + (size_t)(j0 + 0) * d;
        const float* w1 = W + (size_t)(j0 + 1) * d;
        const float* w2 = W + (size_t)(j0 + 2) * d;
        #pragma unroll
        for (int k = 0; k < 4; ++k) {
            if (k < d) {
                acc[k] += c0 * (double)w0[k] + c1 * (double)w1[k] + c2 * (double)w2[k];
            }
        }
    }

    #pragma unroll
    for (int k = 0; k < 4; ++k) red[threadIdx.x * 4 + k] = acc[k];
    __syncthreads();

    for (int offset = 128; offset > 0; offset >>= 1) {
        if (threadIdx.x < offset) {
            #pragma unroll
            for (int k = 0; k < 4; ++k)
                red[threadIdx.x * 4 + k] += red[(threadIdx.x + offset) * 4 + k];
        }
        __syncthreads();
    }

    if (threadIdx.x < d) {
        out[threadIdx.x] = (float)red[threadIdx.x];
    }
}

extern "C" void kernel_launch(void* const* d_in, const int* in_sizes, int n_in,
                              void* d_out, int out_size) {
    const float* X  = (const float*)d_in[0];
    const float* mu = (const float*)d_in[1];
    const float* W  = (const float*)d_in[2];
    float* out = (float*)d_out;

    const int p3 = in_sizes[1];
    const int p  = p3 / 3;                    // 576
    const int d  = in_sizes[2] / p3;          // 4
    const int n_rows = in_sizes[0] / p;       // 200000
    const int p4 = p / 4;                     // 144
    const int two_p = 2 * p;                  // 1152

    // 1) main pass: 2 CTAs/SM, float4 streaming, coalesced partial stores
    const int rows_per_block = (n_rows + GRID_ACCUM - 1) / GRID_ACCUM;
    const int smem_bytes = 2 * 4 * p4 * (int)sizeof(float4);
    accum_kernel<<<GRID_ACCUM, 4 * p4, smem_bytes>>>((const float4*)X, n_rows,
                                                     p4, rows_per_block);

    // 2) fixed-order fp64 reduction of block partials
    reduce_kernel<<<(two_p + 127) / 128, 1024>>>(GRID_ACCUM, two_p);

    // 3) projection
    project_kernel<<<1, 256>>>(mu, W, out, p, d, 1.0 / (double)n_rows);
}

// round 16
// speedup vs baseline: 1.0772x; 1.0772x over previous
#include <cuda_runtime.h>
#include <cuda_bf16.h>

// CumulantSOAP: per-column mean + central 2nd moment of X (200000 x 576 fp32),
// then project (cum - mu) @ W -> (1, 4) fp32.
//
// R14 post-mortem: fused version failed with rel_err=1.0. Root cause: g_partial
// was sized GRID_ACCUM*2*P_MAX/2 = 303104 floats but blocks write
// GRID_ACCUM*2*p = 340992 floats -> OOB stores clobbered the adjacent g_count
// counter, so no block ever saw itself as "last" and out[] was never written.
// Fix: correct allocation (GRID_ACCUM*2*P_MAX, covers any p<=1024) + isolate
// the counter in a 128B-aligned padded struct. Algorithm unchanged:
//   - 296 blocks stream X (LDG.128, 4-deep MLP, 2 CTAs/SM), store fp32
//     partials (fully overwritten every launch -> replay-safe).
//   - threadfence + atomic counter; last-arriving block reduces all 296
//     partials in fixed order (fp32 slot accumulators -> fp64 combine) and
//     does the fp64 projection, writing out[0..3].
//   - Deterministic: fixed reduction order regardless of which block is last;
//     counter self-resets for the next graph replay.

#define P_MAX        1024
#define GRID_ACCUM   296

__device__ float g_partial[GRID_ACCUM * 2 * P_MAX];   // 606208 floats >= 296*1152

struct __align__(128) Counter { unsigned int v; unsigned int pad[31]; };
__device__ Counter g_count = {0u, {0u}};   // own padded line; reset by last block

__global__ void __launch_bounds__(576, 2)
fused_kernel(const float4* __restrict__ X4,
             const float* __restrict__ mu,
             const float* __restrict__ W,
             float* __restrict__ out,
             int n_rows, int p4, int rows_per_block, int d, double inv_n) {
    const int tid  = threadIdx.x;
    const int lane = tid / p4;           // row-lane 0..3
    const int c    = tid % p4;           // quad index 0..p4-1
    const int p    = p4 * 4;             // 576
    const int two_p = 2 * p;             // 1152
    const int two_p4 = two_p / 4;        // 288 quads of partials

    // ---------------- Phase 1: streaming accumulation ----------------
    int r0 = blockIdx.x * rows_per_block;
    int r1 = r0 + rows_per_block;
    if (r1 > n_rows) r1 = n_rows;

    float s0 = 0.f, s1 = 0.f, s2 = 0.f, s3 = 0.f;
    float q0 = 0.f, q1 = 0.f, q2 = 0.f, q3 = 0.f;

    const size_t stride = (size_t)p4;
    int r = r0 + lane;

    for (; r + 12 < r1; r += 16) {
        float4 a = X4[(size_t)r * stride + c];
        float4 b = X4[(size_t)(r + 4) * stride + c];
        float4 e = X4[(size_t)(r + 8) * stride + c];
        float4 f = X4[(size_t)(r + 12) * stride + c];
        s0 += a.x; q0 = fmaf(a.x, a.x, q0);
        s1 += a.y; q1 = fmaf(a.y, a.y, q1);
        s2 += a.z; q2 = fmaf(a.z, a.z, q2);
        s3 += a.w; q3 = fmaf(a.w, a.w, q3);
        s0 += b.x; q0 = fmaf(b.x, b.x, q0);
        s1 += b.y; q1 = fmaf(b.y, b.y, q1);
        s2 += b.z; q2 = fmaf(b.z, b.z, q2);
        s3 += b.w; q3 = fmaf(b.w, b.w, q3);
        s0 += e.x; q0 = fmaf(e.x, e.x, q0);
        s1 += e.y; q1 = fmaf(e.y, e.y, q1);
        s2 += e.z; q2 = fmaf(e.z, e.z, q2);
        s3 += e.w; q3 = fmaf(e.w, e.w, q3);
        s0 += f.x; q0 = fmaf(f.x, f.x, q0);
        s1 += f.y; q1 = fmaf(f.y, f.y, q1);
        s2 += f.z; q2 = fmaf(f.z, f.z, q2);
        s3 += f.w; q3 = fmaf(f.w, f.w, q3);
    }
    for (; r < r1; r += 4) {
        float4 a = X4[(size_t)r * stride + c];
        s0 += a.x; q0 = fmaf(a.x, a.x, q0);
        s1 += a.y; q1 = fmaf(a.y, a.y, q1);
        s2 += a.z; q2 = fmaf(a.z, a.z, q2);
        s3 += a.w; q3 = fmaf(a.w, a.w, q3);
    }

    // Intra-block reduction across the 4 row-lanes (conflict-free).
    extern __shared__ char smem_raw[];           // 18432 B, reused by phase 2
    float4* red_s4  = (float4*)smem_raw;         // [4][p4]
    float4* red_ss4 = red_s4 + 4 * p4;           // [4][p4]

    red_s4 [lane * p4 + c] = make_float4(s0, s1, s2, s3);
    red_ss4[lane * p4 + c] = make_float4(q0, q1, q2, q3);
    __syncthreads();

    {   // thread col finalizes one column; coalesced partial store
        const int col = tid;                     // blockDim == p
        const float* red_s  = (const float*)red_s4;
        const float* red_ss = (const float*)red_ss4;
        float ts = red_s[col] + red_s[p + col] + red_s[2 * p + col] + red_s[3 * p + col];
        float tq = red_ss[col] + red_ss[p + col] + red_ss[2 * p + col] + red_ss[3 * p + col];
        float* dst = g_partial + (size_t)blockIdx.x * two_p;
        dst[col]     = ts;
        dst[p + col] = tq;
    }

    // ---------------- Completion handshake ----------------
    __threadfence();                             // publish partials (all threads)
    __syncthreads();
    __shared__ unsigned int s_is_last;
    if (tid == 0) {
        unsigned int old = atomicAdd(&g_count.v, 1u);
        s_is_last = (old == gridDim.x - 1) ? 1u : 0u;
    }
    __syncthreads();
    if (!s_is_last) return;
    __threadfence();                             // acquire side

    // ---------------- Phase 2 (last block only): reduce partials ----------------
    // 576 threads = 2 chunks x 288 quads; each thread sums 148 float4 partials
    // (L2-resident) in fixed order. fp32 accumulation in 4 independent slot
    // accumulators (37 terms each, rel err ~2e-6) keeps the single-SM tail on
    // the FMA pipe instead of ~10us of fp64 DADDs; slots are combined in
    // fixed-order fp64 at the end.
    const int q  = tid % two_p4;                 // quad 0..287
    const int j  = tid / two_p4;                 // chunk 0..1
    const float4* gp4 = (const float4*)g_partial;

    float u0x = 0.f, u0y = 0.f, u0z = 0.f, u0w = 0.f;   // slot 0
    float u1x = 0.f, u1y = 0.f, u1z = 0.f, u1w = 0.f;   // slot 1
    float u2x = 0.f, u2y = 0.f, u2z = 0.f, u2w = 0.f;   // slot 2
    float u3x = 0.f, u3y = 0.f, u3z = 0.f, u3w = 0.f;   // slot 3
    int b = j;
    for (; b + 6 < GRID_ACCUM; b += 8) {
        float4 x0 = gp4[(size_t)(b    ) * two_p4 + q];
        float4 x1 = gp4[(size_t)(b + 2) * two_p4 + q];
        float4 x2 = gp4[(size_t)(b + 4) * two_p4 + q];
        float4 x3 = gp4[(size_t)(b + 6) * two_p4 + q];
        u0x += x0.x; u0y += x0.y; u0z += x0.z; u0w += x0.w;
        u1x += x1.x; u1y += x1.y; u1z += x1.z; u1w += x1.w;
        u2x += x2.x; u2y += x2.y; u2z += x2.z; u2w += x2.w;
        u3x += x3.x; u3y += x3.y; u3z += x3.z; u3w += x3.w;
    }
    for (; b < GRID_ACCUM; b += 2) {             // not taken for 296, kept generic
        float4 x0 = gp4[(size_t)b * two_p4 + q];
        u0x += x0.x; u0y += x0.y; u0z += x0.z; u0w += x0.w;
    }
    // Fixed-order fp64 combine of the 4 slots.
    double a0 = (((double)u0x + (double)u1x) + (double)u2x) + (double)u3x;
    double a1 = (((double)u0y + (double)u1y) + (double)u2y) + (double)u3y;
    double a2 = (((double)u0z + (double)u1z) + (double)u2z) + (double)u3z;
    double a3 = (((double)u0w + (double)u1w) + (double)u2w) + (double)u3w;

    __syncthreads();                             // smem_raw reuse barrier
    double* sd = (double*)smem_raw;              // [2][two_p] doubles = 18432 B
    sd[j * two_p + q * 4 + 0] = a0;
    sd[j * two_p + q * 4 + 1] = a1;
    sd[j * two_p + q * 4 + 2] = a2;
    sd[j * two_p + q * 4 + 3] = a3;
    __syncthreads();

    // Combine the 2 chunks in place (fixed order -> deterministic).
    for (int i = tid; i < two_p; i += blockDim.x)
        sd[i] += sd[two_p + i];
    __syncthreads();

    // ---------------- Phase 3: projection (fp64) ----------------
    double acc0 = 0.0, acc1 = 0.0, acc2 = 0.0, acc3 = 0.0;
    {
        const int col = tid;                     // each thread one column
        double m   = sd[col] * inv_n;
        double var = sd[p + col] * inv_n - m * m;
        int j0 = 3 * col;
        double c0 = m   - (double)mu[j0 + 0];
        double c1 = 0.0 - (double)mu[j0 + 1];    // mom1 == 0 to fp32 noise
        double c2 = var - (double)mu[j0 + 2];
        const float* w0 = W + (size_t)(j0 + 0) * d;
        const float* w1 = W + (size_t)(j0 + 1) * d;
        const float* w2 = W + (size_t)(j0 + 2) * d;
        if (d > 0) acc0 = c0 * (double)w0[0] + c1 * (double)w1[0] + c2 * (double)w2[0];
        if (d > 1) acc1 = c0 * (double)w0[1] + c1 * (double)w1[1] + c2 * (double)w2[1];
        if (d > 2) acc2 = c0 * (double)w0[2] + c1 * (double)w1[2] + c2 * (double)w2[2];
        if (d > 3) acc3 = c0 * (double)w0[3] + c1 * (double)w1[3] + c2 * (double)w2[3];
    }

    // Warp-shuffle reduce (fixed order), then cross-warp via smem.
    #pragma unroll
    for (int off = 16; off > 0; off >>= 1) {
        acc0 += __shfl_down_sync(0xffffffffu, acc0, off);
        acc1 += __shfl_down_sync(0xffffffffu, acc1, off);
        acc2 += __shfl_down_sync(0xffffffffu, acc2, off);
        acc3 += __shfl_down_sync(0xffffffffu, acc3, off);
    }
    __shared__ double wsum[18 * 4];              // 576/32 = 18 warps
    const int w  = tid >> 5;
    const int ln = tid & 31;
    if (ln == 0) {
        wsum[w * 4 + 0] = acc0;
        wsum[w * 4 + 1] = acc1;
        wsum[w * 4 + 2] = acc2;
        wsum[w * 4 + 3] = acc3;
    }
    __syncthreads();

    if (tid < 4) {
        double t = 0.0;
        const int n_warps = blockDim.x >> 5;
        for (int w2 = 0; w2 < n_warps; ++w2)
            t += wsum[w2 * 4 + tid];
        if (tid < d) out[tid] = (float)t;
    }

    // Reset counter for the next graph replay (only last block runs this).
    if (tid == 0) g_count.v = 0;
}

extern "C" void kernel_launch(void* const* d_in, const int* in_sizes, int n_in,
                              void* d_out, int out_size) {
    const float* X  = (const float*)d_in[0];
    const float* mu = (const float*)d_in[1];
    const float* W  = (const float*)d_in[2];
    float* out = (float*)d_out;

    const int p3 = in_sizes[1];
    const int p  = p3 / 3;                    // 576
    const int d  = in_sizes[2] / p3;          // 4
    const int n_rows = in_sizes[0] / p;       // 200000
    const int p4 = p / 4;                     // 144

    const int rows_per_block = (n_rows + GRID_ACCUM - 1) / GRID_ACCUM;
    const int smem_bytes = 2 * 4 * p4 * (int)sizeof(float4);  // 18432

    fused_kernel<<<GRID_ACCUM, 4 * p4, smem_bytes>>>(
        (const float4*)X, mu, W, out, n_rows, p4, rows_per_block, d,
        1.0 / (double)n_rows);
}